// round 6
// baseline (speedup 1.0000x reference)
#include <cuda_runtime.h>
#include <cuda_bf16.h>

// Problem constants (fixed by setup_inputs)
#define NN 100000
#define EE 1600000
#define DD 128

// -------- static device scratch (no allocations allowed) --------
__device__ __align__(16) float g_buf1[NN * DD];   // h' = dinv * (X W^T)
__device__ __align__(16) float g_buf2[NN * DD];   // layer-1 output
__device__ int   g_deg[NN];        // edge-only in-degree (no self-loop)
__device__ float g_dinv[NN];
__device__ int   g_rowptr[NN + 1];
__device__ int   g_cursor[NN];
__device__ int   g_col[EE];

// ================= CSR build =================

__global__ void deg_init_kernel(int* deg, int n) {
    int i = blockIdx.x * blockDim.x + threadIdx.x;
    if (i < n) deg[i] = 0;
}

__global__ void deg_count_kernel(const int* __restrict__ dst, int* deg, int e) {
    int i = blockIdx.x * blockDim.x + threadIdx.x;
    if (i < e) atomicAdd(&deg[dst[i]], 1);
}

__global__ void dinv_kernel(const int* __restrict__ deg, float* dinv, int n) {
    int i = blockIdx.x * blockDim.x + threadIdx.x;
    if (i < n) dinv[i] = rsqrtf((float)(deg[i] + 1));   // +1 self-loop
}

// Single-block exclusive scan of deg[i] (edge-only) -> rowptr / cursor.
__global__ void scan_kernel(const int* __restrict__ deg, int* rowptr, int* cursor, int n) {
    __shared__ int warp_sums[32];
    __shared__ int s_carry;
    int tid = threadIdx.x, lane = tid & 31, wid = tid >> 5;
    if (tid == 0) s_carry = 0;
    __syncthreads();
    for (int base = 0; base < n; base += 1024) {
        int i = base + tid;
        int v = (i < n) ? deg[i] : 0;
        int x = v;
        #pragma unroll
        for (int off = 1; off < 32; off <<= 1) {
            int t = __shfl_up_sync(0xffffffffu, x, off);
            if (lane >= off) x += t;
        }
        if (lane == 31) warp_sums[wid] = x;
        __syncthreads();
        if (wid == 0) {
            int w = warp_sums[lane];
            #pragma unroll
            for (int off = 1; off < 32; off <<= 1) {
                int t = __shfl_up_sync(0xffffffffu, w, off);
                if (lane >= off) w += t;
            }
            warp_sums[lane] = w;
        }
        __syncthreads();
        int warp_off = (wid == 0) ? 0 : warp_sums[wid - 1];
        int excl = x + warp_off - v;
        int carry = s_carry;
        if (i < n) { rowptr[i] = carry + excl; cursor[i] = carry + excl; }
        __syncthreads();
        if (tid == 1023) s_carry = carry + warp_sums[31];
        __syncthreads();
    }
    if (threadIdx.x == 0) rowptr[n] = s_carry;
}

__global__ void fill_kernel(const int* __restrict__ src, const int* __restrict__ dst,
                            int* cursor, int* col, int e) {
    int i = blockIdx.x * blockDim.x + threadIdx.x;
    if (i < e) {
        int p = atomicAdd(&cursor[dst[i]], 1);
        col[p] = src[i];
    }
}

// ========== GEMM: out[m][c] = dinv[m] * sum_k X[m][k] * W[c][k] ==========
// BM=128 rows/block, full N=128, BK=16 k-tile, double-buffered smem.
// 256 threads, 8x8 micro-tile. Transposed smem Xs[k][m], Ws[k][n] (pad +4).
#define BK 16
#define SM_PAD 4
#define SM_LD (DD + SM_PAD)     // 132
#define NKT (DD / BK)           // 8 k-tiles

__global__ __launch_bounds__(256) void gemm_scale_kernel(
        const float* __restrict__ X, const float* __restrict__ W,
        const float* __restrict__ dinv, float* __restrict__ out, int n) {
    __shared__ float Xs[2][BK][SM_LD];
    __shared__ float Ws[2][BK][SM_LD];

    int tid = threadIdx.x;
    int row0 = blockIdx.x * DD;          // 128 rows per block

    int tx = tid & 15;                   // n-tile: cols tx*8 .. tx*8+7
    int ty = tid >> 4;                   // m-tile: rows ty*8 .. ty*8+7

    // gmem load mapping: 512 float4 per tile, 2 per thread per operand
    int ldr = tid >> 2;                  // 0..63   (row base)
    int lds = tid & 3;                   // 0..3    (k segment)
    int kseg = lds * 4;

    int gr0 = row0 + ldr;
    int gr1 = row0 + ldr + 64;
    bool ok0 = gr0 < n, ok1 = gr1 < n;

    const float* Xp0 = &X[(size_t)gr0 * DD + kseg];
    const float* Xp1 = &X[(size_t)gr1 * DD + kseg];
    const float* Wp0 = &W[(size_t)ldr * DD + kseg];
    const float* Wp1 = &W[(size_t)(ldr + 64) * DD + kseg];

    float acc[8][8];
    #pragma unroll
    for (int i = 0; i < 8; i++)
        #pragma unroll
        for (int j = 0; j < 8; j++) acc[i][j] = 0.f;

    // prologue: load tile 0 into buffer 0
    {
        float4 fx0 = ok0 ? *(const float4*)Xp0 : make_float4(0.f, 0.f, 0.f, 0.f);
        float4 fx1 = ok1 ? *(const float4*)Xp1 : make_float4(0.f, 0.f, 0.f, 0.f);
        float4 fw0 = *(const float4*)Wp0;
        float4 fw1 = *(const float4*)Wp1;
        Xs[0][kseg + 0][ldr] = fx0.x; Xs[0][kseg + 1][ldr] = fx0.y;
        Xs[0][kseg + 2][ldr] = fx0.z; Xs[0][kseg + 3][ldr] = fx0.w;
        Xs[0][kseg + 0][ldr + 64] = fx1.x; Xs[0][kseg + 1][ldr + 64] = fx1.y;
        Xs[0][kseg + 2][ldr + 64] = fx1.z; Xs[0][kseg + 3][ldr + 64] = fx1.w;
        Ws[0][kseg + 0][ldr] = fw0.x; Ws[0][kseg + 1][ldr] = fw0.y;
        Ws[0][kseg + 2][ldr] = fw0.z; Ws[0][kseg + 3][ldr] = fw0.w;
        Ws[0][kseg + 0][ldr + 64] = fw1.x; Ws[0][kseg + 1][ldr + 64] = fw1.y;
        Ws[0][kseg + 2][ldr + 64] = fw1.z; Ws[0][kseg + 3][ldr + 64] = fw1.w;
    }
    __syncthreads();

    int buf = 0;
    #pragma unroll
    for (int t = 0; t < NKT; t++) {
        float4 fx0, fx1, fw0, fw1;
        bool has_next = (t + 1 < NKT);
        if (has_next) {
            int off = (t + 1) * BK;
            fx0 = ok0 ? *(const float4*)(Xp0 + off) : make_float4(0.f, 0.f, 0.f, 0.f);
            fx1 = ok1 ? *(const float4*)(Xp1 + off) : make_float4(0.f, 0.f, 0.f, 0.f);
            fw0 = *(const float4*)(Wp0 + off);
            fw1 = *(const float4*)(Wp1 + off);
        }

        #pragma unroll
        for (int kk = 0; kk < BK; kk++) {
            float a[8], b[8];
            *(float4*)&a[0] = *(const float4*)&Xs[buf][kk][ty * 8];
            *(float4*)&a[4] = *(const float4*)&Xs[buf][kk][ty * 8 + 4];
            *(float4*)&b[0] = *(const float4*)&Ws[buf][kk][tx * 8];
            *(float4*)&b[4] = *(const float4*)&Ws[buf][kk][tx * 8 + 4];
            #pragma unroll
            for (int i = 0; i < 8; i++)
                #pragma unroll
                for (int j = 0; j < 8; j++)
                    acc[i][j] += a[i] * b[j];
        }

        if (has_next) {
            int nb = buf ^ 1;
            Xs[nb][kseg + 0][ldr] = fx0.x; Xs[nb][kseg + 1][ldr] = fx0.y;
            Xs[nb][kseg + 2][ldr] = fx0.z; Xs[nb][kseg + 3][ldr] = fx0.w;
            Xs[nb][kseg + 0][ldr + 64] = fx1.x; Xs[nb][kseg + 1][ldr + 64] = fx1.y;
            Xs[nb][kseg + 2][ldr + 64] = fx1.z; Xs[nb][kseg + 3][ldr + 64] = fx1.w;
            Ws[nb][kseg + 0][ldr] = fw0.x; Ws[nb][kseg + 1][ldr] = fw0.y;
            Ws[nb][kseg + 2][ldr] = fw0.z; Ws[nb][kseg + 3][ldr] = fw0.w;
            Ws[nb][kseg + 0][ldr + 64] = fw1.x; Ws[nb][kseg + 1][ldr + 64] = fw1.y;
            Ws[nb][kseg + 2][ldr + 64] = fw1.z; Ws[nb][kseg + 3][ldr + 64] = fw1.w;
            __syncthreads();
            buf = nb;
        }
    }

    // epilogue: scale by dinv[row], float4 stores
    #pragma unroll
    for (int i = 0; i < 8; i++) {
        int r = row0 + ty * 8 + i;
        if (r < n) {
            float dv = dinv[r];
            #pragma unroll
            for (int j4 = 0; j4 < 2; j4++) {
                float4 o;
                o.x = dv * acc[i][j4 * 4 + 0];
                o.y = dv * acc[i][j4 * 4 + 1];
                o.z = dv * acc[i][j4 * 4 + 2];
                o.w = dv * acc[i][j4 * 4 + 3];
                *(float4*)&out[(size_t)r * DD + tx * 8 + j4 * 4] = o;
            }
        }
    }
}

// ===== Aggregation: warp per node, atomic-free CSR gather-reduce =====
// out[i] = dinv[i] * (hp[i] + sum_{s in N(i)} hp[s]) + bias + perturb[i]
// Inner loop unrolled x8: 8 independent LDG.128 in flight (MLP=8).
__global__ __launch_bounds__(512) void aggregate_kernel(
        const float* __restrict__ hp, const int* __restrict__ rowptr,
        const int* __restrict__ col, const float* __restrict__ dinv,
        const float* __restrict__ bias, const float* __restrict__ perturb,
        float* __restrict__ out, int n) {
    int warp = (blockIdx.x * blockDim.x + threadIdx.x) >> 5;
    int lane = threadIdx.x & 31;
    if (warp >= n) return;
    int i = warp;
    int beg = rowptr[i];
    int end = rowptr[i + 1];
    int c4 = lane * 4;
    int nm1 = n - 1;

    float4 a0 = *(const float4*)&hp[(size_t)i * DD + c4];  // self-loop (hp already dinv-scaled)
    float4 a1 = make_float4(0.f, 0.f, 0.f, 0.f);
    float4 a2 = make_float4(0.f, 0.f, 0.f, 0.f);
    float4 a3 = make_float4(0.f, 0.f, 0.f, 0.f);

    int j = beg;
    for (; j + 8 <= end; j += 8) {
        int s0 = min(__ldg(&col[j + 0]), nm1);
        int s1 = min(__ldg(&col[j + 1]), nm1);
        int s2 = min(__ldg(&col[j + 2]), nm1);
        int s3 = min(__ldg(&col[j + 3]), nm1);
        int s4 = min(__ldg(&col[j + 4]), nm1);
        int s5 = min(__ldg(&col[j + 5]), nm1);
        int s6 = min(__ldg(&col[j + 6]), nm1);
        int s7 = min(__ldg(&col[j + 7]), nm1);
        float4 v0 = *(const float4*)&hp[(size_t)s0 * DD + c4];
        float4 v1 = *(const float4*)&hp[(size_t)s1 * DD + c4];
        float4 v2 = *(const float4*)&hp[(size_t)s2 * DD + c4];
        float4 v3 = *(const float4*)&hp[(size_t)s3 * DD + c4];
        float4 v4 = *(const float4*)&hp[(size_t)s4 * DD + c4];
        float4 v5 = *(const float4*)&hp[(size_t)s5 * DD + c4];
        float4 v6 = *(const float4*)&hp[(size_t)s6 * DD + c4];
        float4 v7 = *(const float4*)&hp[(size_t)s7 * DD + c4];
        a0.x += v0.x; a0.y += v0.y; a0.z += v0.z; a0.w += v0.w;
        a1.x += v1.x; a1.y += v1.y; a1.z += v1.z; a1.w += v1.w;
        a2.x += v2.x; a2.y += v2.y; a2.z += v2.z; a2.w += v2.w;
        a3.x += v3.x; a3.y += v3.y; a3.z += v3.z; a3.w += v3.w;
        a0.x += v4.x; a0.y += v4.y; a0.z += v4.z; a0.w += v4.w;
        a1.x += v5.x; a1.y += v5.y; a1.z += v5.z; a1.w += v5.w;
        a2.x += v6.x; a2.y += v6.y; a2.z += v6.z; a2.w += v6.w;
        a3.x += v7.x; a3.y += v7.y; a3.z += v7.z; a3.w += v7.w;
    }
    for (; j + 2 <= end; j += 2) {
        int s0 = min(__ldg(&col[j + 0]), nm1);
        int s1 = min(__ldg(&col[j + 1]), nm1);
        float4 v0 = *(const float4*)&hp[(size_t)s0 * DD + c4];
        float4 v1 = *(const float4*)&hp[(size_t)s1 * DD + c4];
        a0.x += v0.x; a0.y += v0.y; a0.z += v0.z; a0.w += v0.w;
        a1.x += v1.x; a1.y += v1.y; a1.z += v1.z; a1.w += v1.w;
    }
    if (j < end) {
        int s = min(__ldg(&col[j]), nm1);
        float4 v = *(const float4*)&hp[(size_t)s * DD + c4];
        a2.x += v.x; a2.y += v.y; a2.z += v.z; a2.w += v.w;
    }
    a0.x += a1.x + a2.x + a3.x;
    a0.y += a1.y + a2.y + a3.y;
    a0.z += a1.z + a2.z + a3.z;
    a0.w += a1.w + a2.w + a3.w;

    float dv = dinv[i];
    float4 b = *(const float4*)&bias[c4];
    float4 p = *(const float4*)&perturb[(size_t)i * DD + c4];
    float4 o;
    o.x = dv * a0.x + b.x + p.x;
    o.y = dv * a0.y + b.y + p.y;
    o.z = dv * a0.z + b.z + p.z;
    o.w = dv * a0.w + b.w + p.w;
    *(float4*)&out[(size_t)i * DD + c4] = o;
}

// ================= launch =================

extern "C" void kernel_launch(void* const* d_in, const int* in_sizes, int n_in,
                              void* d_out, int out_size) {
    const float* x             = (const float*)d_in[0];
    const int*   edge_index    = (const int*)d_in[1];
    const float* perturb_first = (const float*)d_in[2];
    const float* perturb_last  = (const float*)d_in[3];
    const float* W1            = (const float*)d_in[4];
    const float* b1            = (const float*)d_in[5];
    const float* W2            = (const float*)d_in[6];
    const float* b2            = (const float*)d_in[7];
    float* out = (float*)d_out;

    int n = in_sizes[0] / DD;       // 100000
    int e = in_sizes[1] / 2;        // 1600000
    const int* src = edge_index;
    const int* dst = edge_index + e;

    float *buf1, *buf2, *dinv;
    int *deg, *rowptr, *cursor, *colp;
    cudaGetSymbolAddress((void**)&buf1, g_buf1);
    cudaGetSymbolAddress((void**)&buf2, g_buf2);
    cudaGetSymbolAddress((void**)&deg, g_deg);
    cudaGetSymbolAddress((void**)&dinv, g_dinv);
    cudaGetSymbolAddress((void**)&rowptr, g_rowptr);
    cudaGetSymbolAddress((void**)&cursor, g_cursor);
    cudaGetSymbolAddress((void**)&colp, g_col);

    const int T = 256;
    int gn = (n + T - 1) / T;
    int ge = (e + T - 1) / T;

    // ---- CSR build (per launch; reused by both layers) ----
    deg_init_kernel<<<gn, T>>>(deg, n);
    deg_count_kernel<<<ge, T>>>(dst, deg, e);
    dinv_kernel<<<gn, T>>>(deg, dinv, n);
    scan_kernel<<<1, 1024>>>(deg, rowptr, cursor, n);
    fill_kernel<<<ge, T>>>(src, dst, cursor, colp, e);

    int g_gemm = (n + DD - 1) / DD;              // 128 rows per block
    int g_agg  = (n * 32 + 511) / 512;           // 512 threads = 16 warps/CTA

    // ---- layer 1 ----
    gemm_scale_kernel<<<g_gemm, T>>>(x, W1, dinv, buf1, n);
    aggregate_kernel<<<g_agg, 512>>>(buf1, rowptr, colp, dinv, b1, perturb_first, buf2, n);

    // ---- layer 2 ----
    gemm_scale_kernel<<<g_gemm, T>>>(buf2, W2, dinv, buf1, n);
    aggregate_kernel<<<g_agg, 512>>>(buf1, rowptr, colp, dinv, b2, perturb_last, out, n);
}

// round 13
// speedup vs baseline: 1.0973x; 1.0973x over previous
#include <cuda_runtime.h>
#include <cuda_bf16.h>

// Problem constants (fixed by setup_inputs)
#define NN 100000
#define EE 1600000
#define DD 128

// multi-block scan config
#define SCAN_T 1024
#define SCAN_ITEMS 4
#define SCAN_CHUNK (SCAN_T * SCAN_ITEMS)          // 4096
#define SCAN_NB ((NN + SCAN_CHUNK - 1) / SCAN_CHUNK)  // 25

// -------- static device scratch (no allocations allowed) --------
__device__ __align__(16) float g_buf1[NN * DD];   // h' = dinv * (X W^T)
__device__ __align__(16) float g_buf2[NN * DD];   // layer-1 output
__device__ __align__(16) int   g_deg[NN + 4];     // edge-only in-degree (padded for int4 init)
__device__ float g_dinv[NN];
__device__ int   g_rowptr[NN + 1];
__device__ int   g_cursor[NN];
__device__ int   g_col[EE];
__device__ int   g_bsum[SCAN_NB];
__device__ int   g_boff[SCAN_NB];

// ================= CSR build =================

__global__ void deg_init_kernel(int4* deg4, int n4) {
    int i = blockIdx.x * blockDim.x + threadIdx.x;
    if (i < n4) deg4[i] = make_int4(0, 0, 0, 0);
}

__global__ void deg_count_kernel(const int* __restrict__ dst, int* deg, int e) {
    int i = blockIdx.x * blockDim.x + threadIdx.x;
    if (i < e) atomicAdd(&deg[dst[i]], 1);
}

// ---- phase 1: per-block sums of deg ----
__global__ void block_sums_kernel(const int* __restrict__ deg, int* bsum, int n) {
    __shared__ int wsum[32];
    int tid = threadIdx.x, lane = tid & 31, wid = tid >> 5;
    int base = blockIdx.x * SCAN_CHUNK;
    int s = 0;
    #pragma unroll
    for (int it = 0; it < SCAN_ITEMS; it++) {
        int i = base + it * SCAN_T + tid;
        if (i < n) s += deg[i];
    }
    #pragma unroll
    for (int off = 16; off > 0; off >>= 1) s += __shfl_down_sync(0xffffffffu, s, off);
    if (lane == 0) wsum[wid] = s;
    __syncthreads();
    if (wid == 0) {
        int v = (lane < SCAN_T / 32) ? wsum[lane] : 0;
        #pragma unroll
        for (int off = 16; off > 0; off >>= 1) v += __shfl_down_sync(0xffffffffu, v, off);
        if (lane == 0) bsum[blockIdx.x] = v;
    }
}

// ---- phase 2: exclusive scan of the 25 block sums (one warp) ----
__global__ void scan_bsums_kernel(const int* __restrict__ bsum, int* boff, int* rowptr_last) {
    int lane = threadIdx.x;
    int v = (lane < SCAN_NB) ? bsum[lane] : 0;
    int x = v;
    #pragma unroll
    for (int off = 1; off < 32; off <<= 1) {
        int t = __shfl_up_sync(0xffffffffu, x, off);
        if (lane >= off) x += t;
    }
    if (lane < SCAN_NB) boff[lane] = x - v;   // exclusive
    if (lane == 31) *rowptr_last = x;          // total
}

// ---- phase 3: local exclusive scan + block offset -> rowptr/cursor + dinv ----
__global__ void local_scan_kernel(const int* __restrict__ deg, const int* __restrict__ boff,
                                  int* rowptr, int* cursor, float* dinv, int n) {
    __shared__ int wsum[32];
    int tid = threadIdx.x, lane = tid & 31, wid = tid >> 5;
    int base = blockIdx.x * SCAN_CHUNK;

    int v[SCAN_ITEMS];
    int tsum = 0;
    #pragma unroll
    for (int it = 0; it < SCAN_ITEMS; it++) {
        int i = base + tid * SCAN_ITEMS + it;   // thread-contiguous items
        v[it] = (i < n) ? deg[i] : 0;
        tsum += v[it];
    }
    // warp inclusive scan of thread sums
    int x = tsum;
    #pragma unroll
    for (int off = 1; off < 32; off <<= 1) {
        int t = __shfl_up_sync(0xffffffffu, x, off);
        if (lane >= off) x += t;
    }
    if (lane == 31) wsum[wid] = x;
    __syncthreads();
    if (wid == 0) {
        int w = (lane < SCAN_T / 32) ? wsum[lane] : 0;
        #pragma unroll
        for (int off = 1; off < 32; off <<= 1) {
            int t = __shfl_up_sync(0xffffffffu, w, off);
            if (lane >= off) w += t;
        }
        if (lane < SCAN_T / 32) wsum[lane] = w;
    }
    __syncthreads();
    int warp_off = (wid == 0) ? 0 : wsum[wid - 1];
    int excl = boff[blockIdx.x] + warp_off + x - tsum;   // exclusive prefix for this thread
    #pragma unroll
    for (int it = 0; it < SCAN_ITEMS; it++) {
        int i = base + tid * SCAN_ITEMS + it;
        if (i < n) {
            rowptr[i] = excl;
            cursor[i] = excl;
            dinv[i] = rsqrtf((float)(v[it] + 1));   // +1 self-loop
        }
        excl += v[it];
    }
}

__global__ void fill_kernel(const int* __restrict__ src, const int* __restrict__ dst,
                            int* cursor, int* col, int e) {
    int i = blockIdx.x * blockDim.x + threadIdx.x;
    if (i < e) {
        int p = atomicAdd(&cursor[dst[i]], 1);
        col[p] = src[i];
    }
}

// ========== GEMM: out[m][c] = dinv[m] * sum_k X[m][k] * W[c][k] ==========
// BM=128 rows/block, full N=128, BK=16 k-tile, double-buffered smem.
// 256 threads, 8x8 micro-tile. Transposed smem Xs[k][m], Ws[k][n] (pad +4).
#define BK 16
#define SM_PAD 4
#define SM_LD (DD + SM_PAD)     // 132
#define NKT (DD / BK)           // 8 k-tiles

__global__ __launch_bounds__(256) void gemm_scale_kernel(
        const float* __restrict__ X, const float* __restrict__ W,
        const float* __restrict__ dinv, float* __restrict__ out, int n) {
    __shared__ float Xs[2][BK][SM_LD];
    __shared__ float Ws[2][BK][SM_LD];

    int tid = threadIdx.x;
    int row0 = blockIdx.x * DD;          // 128 rows per block

    int tx = tid & 15;                   // n-tile: cols tx*8 .. tx*8+7
    int ty = tid >> 4;                   // m-tile: rows ty*8 .. ty*8+7

    int ldr = tid >> 2;                  // 0..63   (row base)
    int lds = tid & 3;                   // 0..3    (k segment)
    int kseg = lds * 4;

    int gr0 = row0 + ldr;
    int gr1 = row0 + ldr + 64;
    bool ok0 = gr0 < n, ok1 = gr1 < n;

    const float* Xp0 = &X[(size_t)gr0 * DD + kseg];
    const float* Xp1 = &X[(size_t)gr1 * DD + kseg];
    const float* Wp0 = &W[(size_t)ldr * DD + kseg];
    const float* Wp1 = &W[(size_t)(ldr + 64) * DD + kseg];

    float acc[8][8];
    #pragma unroll
    for (int i = 0; i < 8; i++)
        #pragma unroll
        for (int j = 0; j < 8; j++) acc[i][j] = 0.f;

    {
        float4 fx0 = ok0 ? *(const float4*)Xp0 : make_float4(0.f, 0.f, 0.f, 0.f);
        float4 fx1 = ok1 ? *(const float4*)Xp1 : make_float4(0.f, 0.f, 0.f, 0.f);
        float4 fw0 = *(const float4*)Wp0;
        float4 fw1 = *(const float4*)Wp1;
        Xs[0][kseg + 0][ldr] = fx0.x; Xs[0][kseg + 1][ldr] = fx0.y;
        Xs[0][kseg + 2][ldr] = fx0.z; Xs[0][kseg + 3][ldr] = fx0.w;
        Xs[0][kseg + 0][ldr + 64] = fx1.x; Xs[0][kseg + 1][ldr + 64] = fx1.y;
        Xs[0][kseg + 2][ldr + 64] = fx1.z; Xs[0][kseg + 3][ldr + 64] = fx1.w;
        Ws[0][kseg + 0][ldr] = fw0.x; Ws[0][kseg + 1][ldr] = fw0.y;
        Ws[0][kseg + 2][ldr] = fw0.z; Ws[0][kseg + 3][ldr] = fw0.w;
        Ws[0][kseg + 0][ldr + 64] = fw1.x; Ws[0][kseg + 1][ldr + 64] = fw1.y;
        Ws[0][kseg + 2][ldr + 64] = fw1.z; Ws[0][kseg + 3][ldr + 64] = fw1.w;
    }
    __syncthreads();

    int buf = 0;
    #pragma unroll
    for (int t = 0; t < NKT; t++) {
        float4 fx0, fx1, fw0, fw1;
        bool has_next = (t + 1 < NKT);
        if (has_next) {
            int off = (t + 1) * BK;
            fx0 = ok0 ? *(const float4*)(Xp0 + off) : make_float4(0.f, 0.f, 0.f, 0.f);
            fx1 = ok1 ? *(const float4*)(Xp1 + off) : make_float4(0.f, 0.f, 0.f, 0.f);
            fw0 = *(const float4*)(Wp0 + off);
            fw1 = *(const float4*)(Wp1 + off);
        }

        #pragma unroll
        for (int kk = 0; kk < BK; kk++) {
            float a[8], b[8];
            *(float4*)&a[0] = *(const float4*)&Xs[buf][kk][ty * 8];
            *(float4*)&a[4] = *(const float4*)&Xs[buf][kk][ty * 8 + 4];
            *(float4*)&b[0] = *(const float4*)&Ws[buf][kk][tx * 8];
            *(float4*)&b[4] = *(const float4*)&Ws[buf][kk][tx * 8 + 4];
            #pragma unroll
            for (int i = 0; i < 8; i++)
                #pragma unroll
                for (int j = 0; j < 8; j++)
                    acc[i][j] += a[i] * b[j];
        }

        if (has_next) {
            int nb = buf ^ 1;
            Xs[nb][kseg + 0][ldr] = fx0.x; Xs[nb][kseg + 1][ldr] = fx0.y;
            Xs[nb][kseg + 2][ldr] = fx0.z; Xs[nb][kseg + 3][ldr] = fx0.w;
            Xs[nb][kseg + 0][ldr + 64] = fx1.x; Xs[nb][kseg + 1][ldr + 64] = fx1.y;
            Xs[nb][kseg + 2][ldr + 64] = fx1.z; Xs[nb][kseg + 3][ldr + 64] = fx1.w;
            Ws[nb][kseg + 0][ldr] = fw0.x; Ws[nb][kseg + 1][ldr] = fw0.y;
            Ws[nb][kseg + 2][ldr] = fw0.z; Ws[nb][kseg + 3][ldr] = fw0.w;
            Ws[nb][kseg + 0][ldr + 64] = fw1.x; Ws[nb][kseg + 1][ldr + 64] = fw1.y;
            Ws[nb][kseg + 2][ldr + 64] = fw1.z; Ws[nb][kseg + 3][ldr + 64] = fw1.w;
            __syncthreads();
            buf = nb;
        }
    }

    #pragma unroll
    for (int i = 0; i < 8; i++) {
        int r = row0 + ty * 8 + i;
        if (r < n) {
            float dv = dinv[r];
            #pragma unroll
            for (int j4 = 0; j4 < 2; j4++) {
                float4 o;
                o.x = dv * acc[i][j4 * 4 + 0];
                o.y = dv * acc[i][j4 * 4 + 1];
                o.z = dv * acc[i][j4 * 4 + 2];
                o.w = dv * acc[i][j4 * 4 + 3];
                *(float4*)&out[(size_t)r * DD + tx * 8 + j4 * 4] = o;
            }
        }
    }
}

// ===== Aggregation: warp per node, atomic-free CSR gather-reduce =====
__global__ __launch_bounds__(512) void aggregate_kernel(
        const float* __restrict__ hp, const int* __restrict__ rowptr,
        const int* __restrict__ col, const float* __restrict__ dinv,
        const float* __restrict__ bias, const float* __restrict__ perturb,
        float* __restrict__ out, int n) {
    int warp = (blockIdx.x * blockDim.x + threadIdx.x) >> 5;
    int lane = threadIdx.x & 31;
    if (warp >= n) return;
    int i = warp;
    int beg = rowptr[i];
    int end = rowptr[i + 1];
    int c4 = lane * 4;
    int nm1 = n - 1;

    float4 a0 = *(const float4*)&hp[(size_t)i * DD + c4];  // self-loop (hp already dinv-scaled)
    float4 a1 = make_float4(0.f, 0.f, 0.f, 0.f);
    float4 a2 = make_float4(0.f, 0.f, 0.f, 0.f);
    float4 a3 = make_float4(0.f, 0.f, 0.f, 0.f);

    int j = beg;
    for (; j + 8 <= end; j += 8) {
        int s0 = min(__ldg(&col[j + 0]), nm1);
        int s1 = min(__ldg(&col[j + 1]), nm1);
        int s2 = min(__ldg(&col[j + 2]), nm1);
        int s3 = min(__ldg(&col[j + 3]), nm1);
        int s4 = min(__ldg(&col[j + 4]), nm1);
        int s5 = min(__ldg(&col[j + 5]), nm1);
        int s6 = min(__ldg(&col[j + 6]), nm1);
        int s7 = min(__ldg(&col[j + 7]), nm1);
        float4 v0 = *(const float4*)&hp[(size_t)s0 * DD + c4];
        float4 v1 = *(const float4*)&hp[(size_t)s1 * DD + c4];
        float4 v2 = *(const float4*)&hp[(size_t)s2 * DD + c4];
        float4 v3 = *(const float4*)&hp[(size_t)s3 * DD + c4];
        float4 v4 = *(const float4*)&hp[(size_t)s4 * DD + c4];
        float4 v5 = *(const float4*)&hp[(size_t)s5 * DD + c4];
        float4 v6 = *(const float4*)&hp[(size_t)s6 * DD + c4];
        float4 v7 = *(const float4*)&hp[(size_t)s7 * DD + c4];
        a0.x += v0.x; a0.y += v0.y; a0.z += v0.z; a0.w += v0.w;
        a1.x += v1.x; a1.y += v1.y; a1.z += v1.z; a1.w += v1.w;
        a2.x += v2.x; a2.y += v2.y; a2.z += v2.z; a2.w += v2.w;
        a3.x += v3.x; a3.y += v3.y; a3.z += v3.z; a3.w += v3.w;
        a0.x += v4.x; a0.y += v4.y; a0.z += v4.z; a0.w += v4.w;
        a1.x += v5.x; a1.y += v5.y; a1.z += v5.z; a1.w += v5.w;
        a2.x += v6.x; a2.y += v6.y; a2.z += v6.z; a2.w += v6.w;
        a3.x += v7.x; a3.y += v7.y; a3.z += v7.z; a3.w += v7.w;
    }
    for (; j + 2 <= end; j += 2) {
        int s0 = min(__ldg(&col[j + 0]), nm1);
        int s1 = min(__ldg(&col[j + 1]), nm1);
        float4 v0 = *(const float4*)&hp[(size_t)s0 * DD + c4];
        float4 v1 = *(const float4*)&hp[(size_t)s1 * DD + c4];
        a0.x += v0.x; a0.y += v0.y; a0.z += v0.z; a0.w += v0.w;
        a1.x += v1.x; a1.y += v1.y; a1.z += v1.z; a1.w += v1.w;
    }
    if (j < end) {
        int s = min(__ldg(&col[j]), nm1);
        float4 v = *(const float4*)&hp[(size_t)s * DD + c4];
        a2.x += v.x; a2.y += v.y; a2.z += v.z; a2.w += v.w;
    }
    a0.x += a1.x + a2.x + a3.x;
    a0.y += a1.y + a2.y + a3.y;
    a0.z += a1.z + a2.z + a3.z;
    a0.w += a1.w + a2.w + a3.w;

    float dv = dinv[i];
    float4 b = *(const float4*)&bias[c4];
    float4 p = *(const float4*)&perturb[(size_t)i * DD + c4];
    float4 o;
    o.x = dv * a0.x + b.x + p.x;
    o.y = dv * a0.y + b.y + p.y;
    o.z = dv * a0.z + b.z + p.z;
    o.w = dv * a0.w + b.w + p.w;
    *(float4*)&out[(size_t)i * DD + c4] = o;
}

// ================= launch =================

extern "C" void kernel_launch(void* const* d_in, const int* in_sizes, int n_in,
                              void* d_out, int out_size) {
    const float* x             = (const float*)d_in[0];
    const int*   edge_index    = (const int*)d_in[1];
    const float* perturb_first = (const float*)d_in[2];
    const float* perturb_last  = (const float*)d_in[3];
    const float* W1            = (const float*)d_in[4];
    const float* b1            = (const float*)d_in[5];
    const float* W2            = (const float*)d_in[6];
    const float* b2            = (const float*)d_in[7];
    float* out = (float*)d_out;

    int n = in_sizes[0] / DD;       // 100000
    int e = in_sizes[1] / 2;        // 1600000
    const int* src = edge_index;
    const int* dst = edge_index + e;

    float *buf1, *buf2, *dinv;
    int *deg, *rowptr, *cursor, *colp, *bsum, *boff;
    cudaGetSymbolAddress((void**)&buf1, g_buf1);
    cudaGetSymbolAddress((void**)&buf2, g_buf2);
    cudaGetSymbolAddress((void**)&deg, g_deg);
    cudaGetSymbolAddress((void**)&dinv, g_dinv);
    cudaGetSymbolAddress((void**)&rowptr, g_rowptr);
    cudaGetSymbolAddress((void**)&cursor, g_cursor);
    cudaGetSymbolAddress((void**)&colp, g_col);
    cudaGetSymbolAddress((void**)&bsum, g_bsum);
    cudaGetSymbolAddress((void**)&boff, g_boff);

    const int T = 256;
    int gn = (n + T - 1) / T;
    int ge = (e + T - 1) / T;

    // ---- CSR build ----
    int n4 = (n + 3) / 4;
    deg_init_kernel<<<(n4 + T - 1) / T, T>>>((int4*)deg, n4);
    deg_count_kernel<<<ge, T>>>(dst, deg, e);
    block_sums_kernel<<<SCAN_NB, SCAN_T>>>(deg, bsum, n);
    scan_bsums_kernel<<<1, 32>>>(bsum, boff, rowptr + n);
    local_scan_kernel<<<SCAN_NB, SCAN_T>>>(deg, boff, rowptr, cursor, dinv, n);
    fill_kernel<<<ge, T>>>(src, dst, cursor, colp, e);

    int g_gemm = (n + DD - 1) / DD;              // 128 rows per block
    int g_agg  = (n * 32 + 511) / 512;           // 512 threads = 16 warps/CTA

    // ---- layer 1 ----
    gemm_scale_kernel<<<g_gemm, T>>>(x, W1, dinv, buf1, n);
    aggregate_kernel<<<g_agg, 512>>>(buf1, rowptr, colp, dinv, b1, perturb_first, buf2, n);

    // ---- layer 2 ----
    gemm_scale_kernel<<<g_gemm, T>>>(buf2, W2, dinv, buf1, n);
    aggregate_kernel<<<g_agg, 512>>>(buf1, rowptr, colp, dinv, b2, perturb_last, out, n);
}